// round 1
// baseline (speedup 1.0000x reference)
#include <cuda_runtime.h>
#include <cuda_bf16.h>
#include <cstdint>

// Problem constants (shapes are fixed by the dataset, but M/N taken from in_sizes)
#define GIBS   32      // 4 kinds * G=8
#define OBS    16
#define KSUP   32
#define MAX_N  100000

// Scratch (static __device__ globals; no allocation at runtime)
__device__ float4 g_pts4[MAX_N];
__device__ float  g_coef[5 * GIBS];   // [0:32)=Ax [32:64)=Ay [64:96)=Az [96:128)=Cc [128:160)=inc

// ---------------------------------------------------------------------------
// Prep: pack points into float4 (aligned 16B gather) + fold GIB params into
// unified quadratic-form coefficients with -0.5*log2(e) baked in (so the
// per-pair exponential is a single ex2.approx).
// ---------------------------------------------------------------------------
__global__ void prep_kernel(const float* __restrict__ pts, int n,
                            const float* __restrict__ cy_r,
                            const float* __restrict__ dk_r,
                            const float* __restrict__ dk_w,
                            const float* __restrict__ cn_r,
                            const float* __restrict__ cn_i,
                            const float* __restrict__ el_r) {
    int i = blockIdx.x * blockDim.x + threadIdx.x;
    if (i < n) {
        g_pts4[i] = make_float4(pts[3*i], pts[3*i+1], pts[3*i+2], 0.f);
    }
    if (i < GIBS) {
        const float NL = -0.72134752044448170f;  // -0.5 * log2(e)
        const float EPS = 1e-8f;
        int kind = i >> 3, gi = i & 7;
        float Ax = 0.f, Ay = 0.f, Az = 0.f, Cc = 0.f, inc = 0.f;
        if (kind == 0) {               // cylinder
            float r = cy_r[gi]; float a = NL / (r*r + EPS);
            Ax = a; Ay = a;
        } else if (kind == 1) {        // cone
            float r = cn_r[gi]; inc = cn_i[gi];
            Cc = NL / (r*r + EPS);
        } else if (kind == 2) {        // disk
            float r = dk_r[gi], w = dk_w[gi];
            float a = NL / (r*r + EPS);
            Ax = a; Ay = a; Az = NL / (w*w + EPS);
        } else {                       // ellipsoid
            float rx = el_r[gi*3+0], ry = el_r[gi*3+1], rz = el_r[gi*3+2];
            Ax = NL / (rx*rx + EPS); Ay = NL / (ry*ry + EPS); Az = NL / (rz*rz + EPS);
        }
        g_coef[i]       = Ax;
        g_coef[32 + i]  = Ay;
        g_coef[64 + i]  = Az;
        g_coef[96 + i]  = Cc;
        g_coef[128 + i] = inc;
    }
}

// ---------------------------------------------------------------------------
// Main: warp per query.
//  Phase A (lane = neighbor): gather, reach mask, ballot-compact rel into smem.
//  Phase B (lane = GIB):      loop over ~8% surviving neighbors, 1 ex2 each.
//  Epilogue:                  32->16 matmul with lambdas (split-half + shfl).
// ---------------------------------------------------------------------------
__global__ __launch_bounds__(256)
void gib_main_kernel(const float* __restrict__ qc,
                     const int*   __restrict__ sidx,
                     const float* __restrict__ lambdas,
                     float*       __restrict__ out,
                     int m_total) {
    __shared__ float lam[GIBS * OBS];            // 512 floats
    __shared__ float shX[8][32], shY[8][32], shZ[8][32];

    int tid  = threadIdx.x;
    int w    = tid >> 5;
    int lane = tid & 31;
    int m    = blockIdx.x * 8 + w;

    // stage lambdas
    for (int t = tid; t < GIBS * OBS; t += 256) lam[t] = lambdas[t];

    // per-lane GIB coefficients (coalesced, L1-resident)
    float Ax  = g_coef[lane];
    float Ay  = g_coef[32 + lane];
    float Az  = g_coef[64 + lane];
    float Cc  = g_coef[96 + lane];
    float inc = g_coef[128 + lane];

    __syncthreads();
    if (m >= m_total) return;

    // ---- Phase A: lane = neighbor k ----
    int   idx = sidx[m * KSUP + lane];           // coalesced
    float4 p  = g_pts4[idx];                     // 1 LDG.128 gather
    float qx = qc[3*m], qy = qc[3*m+1], qz = qc[3*m+2];  // uniform broadcast
    float rx = p.x - qx, ry = p.y - qy, rz = p.z - qz;
    float d2 = rx*rx + ry*ry + rz*rz;
    bool pred = (d2 <= 1.0f);                    // REACH^2 = 1

    unsigned bal = __ballot_sync(0xffffffffu, pred);
    int cnt = __popc(bal);
    if (pred) {
        int rank = __popc(bal & ((1u << lane) - 1u));
        shX[w][rank] = rx; shY[w][rank] = ry; shZ[w][rank] = rz;
    }
    __syncwarp();

    // ---- Phase B: lane = GIB g; loop over compacted neighbors ----
    float acc = 0.f;
    for (int j = 0; j < cnt; ++j) {
        float x = shX[w][j], y = shY[w][j], z = shZ[w][j];   // broadcast LDS
        float x2 = x*x, y2 = y*y, z2 = z*z;
        float xy2e = x2 + y2 + 1e-8f;
        float rxy;
        asm("sqrt.approx.f32 %0, %1;" : "=f"(rxy) : "f"(xy2e));
        float t  = fmaf(z, -inc, rxy);           // r_xy - z*inc
        float arg = fmaf(x2, Ax,
                    fmaf(y2, Ay,
                    fmaf(z2, Az, t * t * Cc)));
        float wv;
        asm("ex2.approx.f32 %0, %1;" : "=f"(wv) : "f"(arg));
        acc += wv;
    }

    // ---- Epilogue: out[m, :] = (acc_vec / K) @ lambdas ----
    __syncwarp();
    shX[w][lane] = acc;
    __syncwarp();

    int o    = lane & 15;
    int half = lane >> 4;
    float s = 0.f;
    #pragma unroll
    for (int g = 0; g < 16; ++g) {
        int gg = half * 16 + g;
        s = fmaf(shX[w][gg], lam[gg * OBS + o], s);
    }
    s += __shfl_xor_sync(0xffffffffu, s, 16);
    if (lane < 16) {
        out[m * OBS + lane] = s * (1.0f / (float)KSUP);
    }
}

// ---------------------------------------------------------------------------
extern "C" void kernel_launch(void* const* d_in, const int* in_sizes, int n_in,
                              void* d_out, int out_size) {
    const float* points = (const float*)d_in[0];
    const float* qc     = (const float*)d_in[1];
    const int*   sidx   = (const int*)  d_in[2];
    const float* cy_r   = (const float*)d_in[3];
    const float* dk_r   = (const float*)d_in[4];
    const float* dk_w   = (const float*)d_in[5];
    const float* cn_r   = (const float*)d_in[6];
    const float* cn_i   = (const float*)d_in[7];
    const float* el_r   = (const float*)d_in[8];
    const float* lam    = (const float*)d_in[9];
    float* out = (float*)d_out;

    int n = in_sizes[0] / 3;   // 100000
    int m = in_sizes[1] / 3;   // 50000

    prep_kernel<<<(n + 255) / 256, 256>>>(points, n, cy_r, dk_r, dk_w, cn_r, cn_i, el_r);
    gib_main_kernel<<<(m + 7) / 8, 256>>>(qc, sidx, lam, out, m);
}

// round 3
// speedup vs baseline: 1.1564x; 1.1564x over previous
#include <cuda_runtime.h>
#include <cuda_bf16.h>
#include <cstdint>

#define GIBS   32      // 4 kinds * G=8
#define OBS    16
#define KSUP   32
#define MAX_N  100000
#define MAX_M  50000
#define QPW    4       // queries per warp

// Scratch (static __device__ globals; no runtime allocation)
__device__ float4 g_pts4[MAX_N];
__device__ float4 g_q4[MAX_M];
__device__ float4 g_coefB[GIBS];   // (Bx,By,Bz,Bw) per GIB, -0.5*log2(e) folded

// ---------------------------------------------------------------------------
// Prep: pack points & queries into float4; fold all 4 GIB kinds into one
// quadratic form  arg = Bx*x^2 + By*y^2 + Bz*z^2 + Bw*(z*r_xy)
// so the per-(neighbor,GIB) cost is 4 FMA + 1 ex2.approx.
//   cylinder: exp(-xy2/(2(r^2+e)))            -> B=(a,a,0,0),      a=NL/(r^2+e)
//   cone:     exp(-(rxy - inc z)^2/(2(r^2+e)))-> B=(c,c,c*inc^2,-2c*inc)
//   disk:     exp(-(xy2/(r^2+e)+z^2/(w^2+e))/2)->B=(a,a,aw,0)
//   ellip:    per-axis                        -> B=(Ax,Ay,Az,0)
// with NL = -0.5*log2(e) so weight = ex2(arg).
// ---------------------------------------------------------------------------
__global__ void prep_kernel(const float* __restrict__ pts, int n,
                            const float* __restrict__ qcs, int m,
                            const float* __restrict__ cy_r,
                            const float* __restrict__ dk_r,
                            const float* __restrict__ dk_w,
                            const float* __restrict__ cn_r,
                            const float* __restrict__ cn_i,
                            const float* __restrict__ el_r) {
    int i = blockIdx.x * blockDim.x + threadIdx.x;
    if (i < n) g_pts4[i] = make_float4(pts[3*i], pts[3*i+1], pts[3*i+2], 0.f);
    if (i < m) g_q4[i]   = make_float4(qcs[3*i], qcs[3*i+1], qcs[3*i+2], 0.f);
    if (i < GIBS) {
        const float NL  = -0.72134752044448170f;  // -0.5 * log2(e)
        const float EPS = 1e-8f;
        int kind = i >> 3, gi = i & 7;
        float Bx = 0.f, By = 0.f, Bz = 0.f, Bw = 0.f;
        if (kind == 0) {                       // cylinder
            float r = cy_r[gi]; float a = NL / (r*r + EPS);
            Bx = a; By = a;
        } else if (kind == 1) {                // cone
            float r = cn_r[gi], inc = cn_i[gi];
            float c = NL / (r*r + EPS);
            Bx = c; By = c; Bz = c * inc * inc; Bw = -2.f * c * inc;
        } else if (kind == 2) {                // disk
            float r = dk_r[gi], w = dk_w[gi];
            float a = NL / (r*r + EPS);
            Bx = a; By = a; Bz = NL / (w*w + EPS);
        } else {                               // ellipsoid
            float rx = el_r[gi*3+0], ry = el_r[gi*3+1], rz = el_r[gi*3+2];
            Bx = NL / (rx*rx + EPS); By = NL / (ry*ry + EPS); Bz = NL / (rz*rz + EPS);
        }
        g_coefB[i] = make_float4(Bx, By, Bz, Bw);
    }
}

// ---------------------------------------------------------------------------
// Main: warp per QPW queries. Per query:
//  Phase A (lane=neighbor): gather point, reach mask, ballot-compact features
//                           f=(x2,y2,z2,z*rxy) into shared (float4).
//  Phase B (lane=GIB):      loop over ~8% survivors: LDS.128 + 4 FMA + ex2.
//  Epilogue:                lambda in registers; 16 shfl + 16 FMA + xor16.
// ---------------------------------------------------------------------------
__global__ __launch_bounds__(256)
void gib_main_kernel(const int*   __restrict__ sidx,
                     const float* __restrict__ lambdas,
                     float*       __restrict__ out,
                     int m_total) {
    __shared__ float4 shF[8][32];   // 4KB

    int tid  = threadIdx.x;
    int w    = tid >> 5;
    int lane = tid & 31;
    int o    = lane & 15;
    int half = lane >> 4;

    // per-lane GIB coefficients (one LDG.128, L1/L2-resident)
    float4 B = g_coefB[lane];

    // lambda column for this lane's (half, o): 16 registers, loaded once
    float lamr[16];
    #pragma unroll
    for (int g = 0; g < 16; ++g)
        lamr[g] = __ldg(&lambdas[((half << 4) + g) * OBS + o]);

    int m0 = (blockIdx.x * 8 + w) * QPW;

    #pragma unroll 1
    for (int qi = 0; qi < QPW; ++qi) {
        int m = m0 + qi;
        if (m >= m_total) break;

        // ---- Phase A: lane = neighbor ----
        int    idx = sidx[m * KSUP + lane];        // coalesced 128B
        float4 p   = g_pts4[idx];                  // random 16B gather
        float4 q   = g_q4[m];                      // uniform broadcast
        float rx = p.x - q.x, ry = p.y - q.y, rz = p.z - q.z;
        float x2 = rx*rx, y2 = ry*ry, z2 = rz*rz;
        float xy2 = x2 + y2;
        float d2  = xy2 + z2;
        bool pred = (d2 <= 1.0f);                  // REACH^2

        unsigned bal = __ballot_sync(0xffffffffu, pred);
        int cnt = __popc(bal);
        if (pred) {
            float rxy;
            asm("sqrt.approx.f32 %0, %1;" : "=f"(rxy) : "f"(xy2 + 1e-8f));
            int rank = __popc(bal & ((1u << lane) - 1u));
            shF[w][rank] = make_float4(x2, y2, z2, rz * rxy);
        }
        __syncwarp();

        // ---- Phase B: lane = GIB ----
        float acc = 0.f;
        for (int j = 0; j < cnt; ++j) {
            float4 f = shF[w][j];                  // LDS.128 broadcast
            float arg = fmaf(f.x, B.x,
                        fmaf(f.y, B.y,
                        fmaf(f.z, B.z, f.w * B.w)));
            float wv;
            asm("ex2.approx.f32 %0, %1;" : "=f"(wv) : "f"(arg));
            acc += wv;
        }
        __syncwarp();   // shF reusable next query

        // ---- Epilogue: out[m,:] = (acc_vec / K) @ lambda  (register lambda) ----
        float s = 0.f;
        #pragma unroll
        for (int g = 0; g < 16; ++g) {
            float a = __shfl_sync(0xffffffffu, acc, (half << 4) + g);
            s = fmaf(a, lamr[g], s);
        }
        s += __shfl_xor_sync(0xffffffffu, s, 16);
        if (lane < 16)
            out[m * OBS + lane] = s * (1.0f / (float)KSUP);
    }
}

// ---------------------------------------------------------------------------
extern "C" void kernel_launch(void* const* d_in, const int* in_sizes, int n_in,
                              void* d_out, int out_size) {
    const float* points = (const float*)d_in[0];
    const float* qc     = (const float*)d_in[1];
    const int*   sidx   = (const int*)  d_in[2];
    const float* cy_r   = (const float*)d_in[3];
    const float* dk_r   = (const float*)d_in[4];
    const float* dk_w   = (const float*)d_in[5];
    const float* cn_r   = (const float*)d_in[6];
    const float* cn_i   = (const float*)d_in[7];
    const float* el_r   = (const float*)d_in[8];
    const float* lam    = (const float*)d_in[9];
    float* out = (float*)d_out;

    int n = in_sizes[0] / 3;   // 100000
    int m = in_sizes[1] / 3;   // 50000

    int pmax = n > m ? n : m;
    prep_kernel<<<(pmax + 255) / 256, 256>>>(points, n, qc, m,
                                             cy_r, dk_r, dk_w, cn_r, cn_i, el_r);

    int queries_per_block = 8 * QPW;
    gib_main_kernel<<<(m + queries_per_block - 1) / queries_per_block, 256>>>(
        sidx, lam, out, m);
}